// round 13
// baseline (speedup 1.0000x reference)
#include <cuda_runtime.h>
#include <cuda_fp16.h>
#include <cstdint>
#include <math.h>

#define NB   2
#define NTOK 2112
#define NCH  1024
#define NH   16
#define HDIM 64
#define NSEG_T0 64
#define NSEG_T1 1024

// ---------------- scratch (static device globals: no allocation) ----------------
// fp16 operands: A-side single, B-side hi/lo split
__device__ __align__(16) __half g_xa [(size_t)NB * NTOK * NCH];
__device__ __align__(16) __half g_wqh[(size_t)3 * 3 * NCH * NCH];
__device__ __align__(16) __half g_wql[(size_t)3 * 3 * NCH * NCH];
__device__ __align__(16) __half g_wph[(size_t)3 * NCH * NCH];
__device__ __align__(16) __half g_wpl[(size_t)3 * NCH * NCH];
__device__ __align__(16) __half g_ao [(size_t)NB * NTOK * NCH];
// q single; k/v hi/lo, layout [B,H,N,64]
__device__ __align__(16) __half g_qa[(size_t)NB * NH * NTOK * HDIM];
__device__ __align__(16) __half g_kh[(size_t)NB * NH * NTOK * HDIM];
__device__ __align__(16) __half g_kl[(size_t)NB * NH * NTOK * HDIM];
__device__ __align__(16) __half g_vh[(size_t)NB * NH * NTOK * HDIM];
__device__ __align__(16) __half g_vl[(size_t)NB * NH * NTOK * HDIM];
// RoPE LUT: cos/sin per (b, token, dim-pair)
__device__ float g_ct[(size_t)NB * NTOK * 32];
__device__ float g_st[(size_t)NB * NTOK * 32];

// ---------------- PTX helpers ---------------------------------------------------
__device__ __forceinline__ uint32_t smem_u32(const void* p) {
    uint32_t a;
    asm("{ .reg .u64 t; cvta.to.shared.u64 t, %1; cvt.u32.u64 %0, t; }" : "=r"(a) : "l"(p));
    return a;
}
__device__ __forceinline__ void cp16(uint32_t dst, const void* src) {
    asm volatile("cp.async.cg.shared.global [%0], [%1], 16;" :: "r"(dst), "l"(src));
}
#define CP_COMMIT() asm volatile("cp.async.commit_group;" ::: "memory")
#define CP_WAIT(n)  asm volatile("cp.async.wait_group %0;" :: "n"(n) : "memory")

__device__ __forceinline__ void ldm_x4(uint32_t& r0, uint32_t& r1, uint32_t& r2, uint32_t& r3,
                                       uint32_t addr) {
    asm volatile("ldmatrix.sync.aligned.m8n8.x4.shared.b16 {%0,%1,%2,%3}, [%4];"
                 : "=r"(r0), "=r"(r1), "=r"(r2), "=r"(r3) : "r"(addr));
}
__device__ __forceinline__ void ldm_x4_t(uint32_t& r0, uint32_t& r1, uint32_t& r2, uint32_t& r3,
                                         uint32_t addr) {
    asm volatile("ldmatrix.sync.aligned.m8n8.x4.trans.shared.b16 {%0,%1,%2,%3}, [%4];"
                 : "=r"(r0), "=r"(r1), "=r"(r2), "=r"(r3) : "r"(addr));
}
__device__ __forceinline__ void mma_f16(float& c0, float& c1, float& c2, float& c3,
                                        uint32_t a0, uint32_t a1, uint32_t a2, uint32_t a3,
                                        uint32_t b0, uint32_t b1) {
    asm volatile(
        "mma.sync.aligned.m16n8k16.row.col.f32.f16.f16.f32 "
        "{%0,%1,%2,%3}, {%4,%5,%6,%7}, {%8,%9}, {%0,%1,%2,%3};"
        : "+f"(c0), "+f"(c1), "+f"(c2), "+f"(c3)
        : "r"(a0), "r"(a1), "r"(a2), "r"(a3), "r"(b0), "r"(b1));
}
__device__ __forceinline__ uint32_t packh(float lo, float hi) {
    __half2 h = __floats2half2_rn(lo, hi);
    return *(uint32_t*)&h;
}

// ------- row-tile mapping: 17 tiles per batch (seg0:1x64, seg1:8x128, seg2:8x128)
__device__ __forceinline__ void tile_map(int ty, int& seg, int& rowstart, int& rows)
{
    if (ty == 0)      { seg = 0; rowstart = 0;                     rows = 64;  }
    else if (ty < 9)  { seg = 1; rowstart = 64   + (ty - 1) * 128; rows = 128; }
    else              { seg = 2; rowstart = 1088 + (ty - 9) * 128; rows = 128; }
}

// ---------------- fp32 -> fp16 converts ------------------------------------------
__global__ void cvt_half(const float* __restrict__ src, __half* __restrict__ dst, long n4)
{
    long stride = (long)gridDim.x * blockDim.x;
    for (long i = blockIdx.x * (long)blockDim.x + threadIdx.x; i < n4; i += stride) {
        float4 v = *(const float4*)(src + i * 4);
        *(uint2*)(dst + i * 4) = make_uint2(packh(v.x, v.y), packh(v.z, v.w));
    }
}
__global__ void cvt_split(const float* __restrict__ src, __half* __restrict__ hi,
                          __half* __restrict__ lo, long n4)
{
    long stride = (long)gridDim.x * blockDim.x;
    for (long i = blockIdx.x * (long)blockDim.x + threadIdx.x; i < n4; i += stride) {
        float4 v = *(const float4*)(src + i * 4);
        float h0 = __half2float(__float2half_rn(v.x));
        float h1 = __half2float(__float2half_rn(v.y));
        float h2 = __half2float(__float2half_rn(v.z));
        float h3 = __half2float(__float2half_rn(v.w));
        *(uint2*)(hi + i * 4) = make_uint2(packh(h0, h1), packh(h2, h3));
        *(uint2*)(lo + i * 4) = make_uint2(packh(v.x - h0, v.y - h1),
                                           packh(v.z - h2, v.w - h3));
    }
}

// ---------------- RoPE LUT build (fp32 trig) --------------------------------------
__global__ void build_rope_lut(const int* __restrict__ pos_ids,
                               const int* __restrict__ tpos_ids)
{
    int idx = blockIdx.x * blockDim.x + threadIdx.x;
    if (idx >= NB * NTOK * 32) return;
    int dd = idx & 31;
    int t = (idx >> 5) % NTOK;
    int b = idx / (NTOK * 32);
    int pos = (t < NSEG_T0) ? tpos_ids[b * NSEG_T0 + t]
                            : pos_ids[b * (NTOK - NSEG_T0) + (t - NSEG_T0)];
    float inv = 1.0f / powf(10000.0f, (float)dd / 32.0f);
    float ang = (float)pos * inv;
    float s, c;
    sincosf(ang, &s, &c);
    g_ct[idx] = c;
    g_st[idx] = s;
}

// ---------------- warp-mma GEMM mainloop: 128x128, 256 thr, 3-stage pipeline -----
#define KTILE 64
#define NSTAGE (NCH / KTILE)          // 16
#define SROWB 144
#define ARR_BYTES (128 * SROWB)
#define STAGE_BYTES (3 * ARR_BYTES)   // A, Bh, Bl
#define GSMEM (3 * STAGE_BYTES)       // 165888 (3 pipeline stages)

__device__ __forceinline__ void load_stage(uint32_t sb,
                                           const __half* __restrict__ A,
                                           const __half* __restrict__ Bh,
                                           const __half* __restrict__ Bl,
                                           int k0, int Mrem)
{
    const int tid = threadIdx.x;
#pragma unroll
    for (int i = 0; i < 4; i++) {
        int idx = tid + i * 256;
        int row = idx >> 3;
        int c16 = idx & 7;
        int ar  = row < Mrem ? row : Mrem - 1;
        size_t aoff = (size_t)ar * NCH + k0 + c16 * 8;
        size_t boff = (size_t)row * NCH + k0 + c16 * 8;
        uint32_t d = sb + row * SROWB + c16 * 16;
        cp16(d,                 A  + aoff);
        cp16(d + ARR_BYTES,     Bh + boff);
        cp16(d + 2 * ARR_BYTES, Bl + boff);
    }
}

__device__ __forceinline__ void gemm_mainloop(const __half* __restrict__ A,
                                              const __half* __restrict__ Bh,
                                              const __half* __restrict__ Bl,
                                              int Mrem, float acc[2][8][4])
{
    extern __shared__ char dsm[];
    uint32_t sb = smem_u32(dsm);
    const int tid = threadIdx.x, wid = tid >> 5, lane = tid & 31;
    const int m0w = (wid & 3) * 32;
    const int n0w = (wid >> 2) * 64;

#pragma unroll
    for (int mi = 0; mi < 2; mi++)
#pragma unroll
        for (int nj = 0; nj < 8; nj++)
#pragma unroll
            for (int r = 0; r < 4; r++) acc[mi][nj][r] = 0.f;

    const int a_row = (lane & 15);
    const int a_kh  = (lane >> 4) << 3;
    const int b_row = (lane & 7) + ((lane >> 4) << 3);
    const int b_kh  = ((lane >> 3) & 1) << 3;

    // prologue: prefetch stages 0 and 1
    load_stage(sb, A, Bh, Bl, 0, Mrem);
    CP_COMMIT();
    load_stage(sb + STAGE_BYTES, A, Bh, Bl, KTILE, Mrem);
    CP_COMMIT();

    int bufc = 0;  // buffer of current stage
    for (int s = 0; s < NSTAGE; ++s) {
        uint32_t cb = sb + bufc * STAGE_BYTES;
        if (s + 2 < NSTAGE) {
            int bufn = bufc - 1; if (bufn < 0) bufn = 2;   // (s+2)%3
            load_stage(sb + bufn * STAGE_BYTES, A, Bh, Bl, (s + 2) * KTILE, Mrem);
            CP_COMMIT();
            CP_WAIT(2);
        } else if (s + 1 < NSTAGE) {
            CP_WAIT(1);
        } else {
            CP_WAIT(0);
        }
        __syncthreads();

#pragma unroll
        for (int kk = 0; kk < 4; ++kk) {
            uint32_t af[2][4], bh[8][2], bl[8][2];
#pragma unroll
            for (int mi = 0; mi < 2; mi++) {
                uint32_t addr = cb + (m0w + mi * 16 + a_row) * SROWB + (kk * 16 + a_kh) * 2;
                ldm_x4(af[mi][0], af[mi][1], af[mi][2], af[mi][3], addr);
            }
#pragma unroll
            for (int p = 0; p < 4; p++) {
                uint32_t addr = cb + ARR_BYTES
                              + (n0w + p * 16 + b_row) * SROWB + (kk * 16 + b_kh) * 2;
                ldm_x4(bh[2 * p][0], bh[2 * p][1], bh[2 * p + 1][0], bh[2 * p + 1][1], addr);
                ldm_x4(bl[2 * p][0], bl[2 * p][1], bl[2 * p + 1][0], bl[2 * p + 1][1],
                       addr + ARR_BYTES);
            }
#pragma unroll
            for (int mi = 0; mi < 2; mi++)
#pragma unroll
                for (int nj = 0; nj < 8; nj++) {
                    float* c = acc[mi][nj];
                    mma_f16(c[0], c[1], c[2], c[3],
                            af[mi][0], af[mi][1], af[mi][2], af[mi][3],
                            bh[nj][0], bh[nj][1]);
                    mma_f16(c[0], c[1], c[2], c[3],
                            af[mi][0], af[mi][1], af[mi][2], af[mi][3],
                            bl[nj][0], bl[nj][1]);
                }
        }
        __syncthreads();
        bufc = (bufc + 1 == 3) ? 0 : bufc + 1;
    }
}

// ---------------- QKV GEMM + fused LN/RoPE/scatter epilogue ----------------------
__global__ __launch_bounds__(256, 1) void qkv_mma(const float* __restrict__ qkv_b,
                                                  const float* __restrict__ qn_w,
                                                  const float* __restrict__ qn_b,
                                                  const float* __restrict__ kn_w,
                                                  const float* __restrict__ kn_b)
{
    int y = blockIdx.y;
    int b = y / 17, t17 = y % 17;
    int seg, rowstart, rows;
    tile_map(t17, seg, rowstart, rows);
    int n0 = blockIdx.x * 128;
    size_t arow = (size_t)(b * NTOK + rowstart) * NCH;
    size_t brow = (size_t)(seg * 3 * NCH + n0) * NCH;

    float acc[2][8][4];
    gemm_mainloop(g_xa + arow, g_wqh + brow, g_wql + brow, rows, acc);

    const int tid = threadIdx.x, wid = tid >> 5, lane = tid & 31;
    const int m0w = (wid & 3) * 32;
    const int n0w = (wid >> 2) * 64;
    const int grp = lane >> 2, tig = lane & 3;

    const int gn = n0 + n0w;              // global output col base (multiple of 64)
    const int part = gn >> 10;            // 0=q, 1=k, 2=v
    const int hd = (gn & 1023) >> 6;      // head index
    const float* bias = qkv_b + seg * 3 * NCH + gn;
    const float* wln = (part == 0) ? qn_w + seg * 64 : kn_w + seg * 64;
    const float* bln = (part == 0) ? qn_b + seg * 64 : kn_b + seg * 64;

#pragma unroll
    for (int mi = 0; mi < 2; mi++) {
#pragma unroll
        for (int r = 0; r < 2; r++) {
            int row = m0w + mi * 16 + grp + r * 8;
            bool valid = row < rows;
            int t = rowstart + row;
            size_t ob = ((size_t)(b * NH + hd) * NTOK + t) * HDIM;

            float yv[8][2];
#pragma unroll
            for (int nj = 0; nj < 8; nj++) {
                int d = nj * 8 + tig * 2;
                yv[nj][0] = acc[mi][nj][2 * r]     + bias[d];
                yv[nj][1] = acc[mi][nj][2 * r + 1] + bias[d + 1];
            }

            if (part == 2) {
                if (valid) {
#pragma unroll
                    for (int nj = 0; nj < 8; nj++) {
                        int d = nj * 8 + tig * 2;
                        float v0 = yv[nj][0], v1 = yv[nj][1];
                        float h0 = __half2float(__float2half_rn(v0));
                        float h1 = __half2float(__float2half_rn(v1));
                        *(uint32_t*)(g_vh + ob + d) = packh(v0, v1);
                        *(uint32_t*)(g_vl + ob + d) = packh(v0 - h0, v1 - h1);
                    }
                }
            } else {
                float s = 0.f;
#pragma unroll
                for (int nj = 0; nj < 8; nj++) s += yv[nj][0] + yv[nj][1];
                s += __shfl_xor_sync(0xffffffffu, s, 1);
                s += __shfl_xor_sync(0xffffffffu, s, 2);
                float mu = s * (1.f / 64.f);
                float s2 = 0.f;
#pragma unroll
                for (int nj = 0; nj < 8; nj++) {
                    float d0 = yv[nj][0] - mu, d1 = yv[nj][1] - mu;
                    s2 += d0 * d0 + d1 * d1;
                }
                s2 += __shfl_xor_sync(0xffffffffu, s2, 1);
                s2 += __shfl_xor_sync(0xffffffffu, s2, 2);
                float istd = rsqrtf(s2 * (1.f / 64.f) + 1e-5f);
#pragma unroll
                for (int nj = 0; nj < 8; nj++) {
                    int d = nj * 8 + tig * 2;
                    yv[nj][0] = (yv[nj][0] - mu) * istd * wln[d]     + bln[d];
                    yv[nj][1] = (yv[nj][1] - mu) * istd * wln[d + 1] + bln[d + 1];
                }
                const float* ctp = g_ct + ((size_t)(b * NTOK) + t) * 32;
                const float* stp = g_st + ((size_t)(b * NTOK) + t) * 32;
#pragma unroll
                for (int nj = 0; nj < 4; nj++) {
                    int d = nj * 8 + tig * 2;
                    float cs0 = ctp[d], sn0 = stp[d];
                    float cs1 = ctp[d + 1], sn1 = stp[d + 1];
                    float a0 = yv[nj][0], a1 = yv[nj][1];
                    float b0 = yv[nj + 4][0], b1 = yv[nj + 4][1];
                    yv[nj][0]     = a0 * cs0 - b0 * sn0;
                    yv[nj][1]     = a1 * cs1 - b1 * sn1;
                    yv[nj + 4][0] = b0 * cs0 + a0 * sn0;
                    yv[nj + 4][1] = b1 * cs1 + a1 * sn1;
                }
                if (valid) {
                    if (part == 0) {
#pragma unroll
                        for (int nj = 0; nj < 8; nj++) {
                            int d = nj * 8 + tig * 2;
                            *(uint32_t*)(g_qa + ob + d) = packh(yv[nj][0], yv[nj][1]);
                        }
                    } else {
#pragma unroll
                        for (int nj = 0; nj < 8; nj++) {
                            int d = nj * 8 + tig * 2;
                            float v0 = yv[nj][0], v1 = yv[nj][1];
                            float h0 = __half2float(__float2half_rn(v0));
                            float h1 = __half2float(__float2half_rn(v1));
                            *(uint32_t*)(g_kh + ob + d) = packh(v0, v1);
                            *(uint32_t*)(g_kl + ob + d) = packh(v0 - h0, v1 - h1);
                        }
                    }
                }
            }
        }
    }
}

// ---------------- proj GEMM (fp32 bias epilogue) ----------------------------------
__global__ __launch_bounds__(256, 1) void proj_mma(const float* __restrict__ proj_b,
                                                   float* __restrict__ out)
{
    int y = blockIdx.y;
    int b = y / 17, t17 = y % 17;
    int seg, rowstart, rows;
    tile_map(t17, seg, rowstart, rows);
    int n0 = blockIdx.x * 128;
    size_t arow = (size_t)(b * NTOK + rowstart) * NCH;
    size_t brow = (size_t)(seg * NCH + n0) * NCH;

    float acc[2][8][4];
    gemm_mainloop(g_ao + arow, g_wph + brow, g_wpl + brow, rows, acc);

    const int tid = threadIdx.x, wid = tid >> 5, lane = tid & 31;
    const int m0w = (wid & 3) * 32;
    const int n0w = (wid >> 2) * 64;
    const int grp = lane >> 2, tig = lane & 3;
    const float* bias = proj_b + seg * NCH + n0;
    float* Cout = out + (size_t)(b * NTOK + rowstart) * NCH + n0;

#pragma unroll
    for (int mi = 0; mi < 2; mi++) {
        int r0 = m0w + mi * 16 + grp;
        int r1 = r0 + 8;
#pragma unroll
        for (int nj = 0; nj < 8; nj++) {
            int n = n0w + nj * 8 + tig * 2;
            float b0 = bias[n], b1 = bias[n + 1];
            if (r0 < rows) {
                float2 v = make_float2(acc[mi][nj][0] + b0, acc[mi][nj][1] + b1);
                *(float2*)(Cout + (size_t)r0 * NCH + n) = v;
            }
            if (r1 < rows) {
                float2 v = make_float2(acc[mi][nj][2] + b0, acc[mi][nj][3] + b1);
                *(float2*)(Cout + (size_t)r1 * NCH + n) = v;
            }
        }
    }
}

// ---------------- flash attention: 64-q tiles, 128 thr, desc schedule ------------
#define FROWB 144
#define FARR  (64 * FROWB)          // 9216
#define FSMEM (9 * FARR)            // 82944

__device__ __forceinline__ void load_kv_stage(uint32_t dst, size_t hb, int t0)
{
    const int tid = threadIdx.x;
#pragma unroll
    for (int i = 0; i < 4; i++) {
        int idx = tid + i * 128;
        int row = idx >> 3;
        int c16 = idx & 7;
        size_t off = hb + (size_t)(t0 + row) * HDIM + c16 * 8;
        uint32_t d = dst + row * FROWB + c16 * 16;
        cp16(d,            g_kh + off);
        cp16(d + FARR,     g_kl + off);
        cp16(d + 2 * FARR, g_vh + off);
        cp16(d + 3 * FARR, g_vl + off);
    }
}

__global__ __launch_bounds__(128, 2) void flash_mma()
{
    extern __shared__ char fsm[];
    uint32_t sb = smem_u32(fsm);
    const uint32_t Qs = sb;
    const uint32_t KV = sb + FARR;

    const int qt = (gridDim.x - 1) - blockIdx.x;   // big tiles first
    const int h = blockIdx.y, b = blockIdx.z;
    const int q0 = qt * 64;
    const int tid = threadIdx.x, wid = tid >> 5, lane = tid & 31;
    const size_t hb = ((size_t)(b * NH + h)) * NTOK * HDIM;

#pragma unroll
    for (int i = 0; i < 4; i++) {
        int idx = tid + i * 128;
        int row = idx >> 3;
        int c16 = idx & 7;
        size_t off = hb + (size_t)(q0 + row) * HDIM + c16 * 8;
        if (idx < 512)
            cp16(Qs + row * FROWB + c16 * 16, g_qa + off);
    }
    CP_COMMIT();
    load_kv_stage(KV, hb, 0);
    CP_COMMIT();
    CP_WAIT(1);
    __syncthreads();

    const int a_row = lane & 15;
    const int a_kh  = (lane >> 4) << 3;
    uint32_t qf[4][4];
#pragma unroll
    for (int kk = 0; kk < 4; kk++) {
        uint32_t addr = Qs + (wid * 16 + a_row) * FROWB + (kk * 16 + a_kh) * 2;
        ldm_x4(qf[kk][0], qf[kk][1], qf[kk][2], qf[kk][3], addr);
    }

    const int grp = lane >> 2, tig = lane & 3;
    const int b_row = (lane & 7) + ((lane >> 4) << 3);
    const int b_kh  = ((lane >> 3) & 1) << 3;
    const int v_row = (lane & 7) + (((lane >> 3) & 1) << 3);
    const int v_col = (lane >> 4) << 3;
    const int row0g = q0 + wid * 16 + grp;

    float m_[2] = {-1e30f, -1e30f}, l_[2] = {0.f, 0.f};
    float o[8][4];
#pragma unroll
    for (int nj = 0; nj < 8; nj++)
#pragma unroll
        for (int r = 0; r < 4; r++) o[nj][r] = 0.f;

    for (int kt = 0; kt <= qt; ++kt) {
        uint32_t st = KV + (kt & 1) * 4 * FARR;
        if (kt < qt) {
            load_kv_stage(KV + ((kt + 1) & 1) * 4 * FARR, hb, (kt + 1) * 64);
            CP_COMMIT();
            CP_WAIT(1);
        } else {
            CP_WAIT(0);
        }
        __syncthreads();

        // ---- S = Q (Kh + Kl)^T ----
        float s[8][4];
#pragma unroll
        for (int nj = 0; nj < 8; nj++)
#pragma unroll
            for (int r = 0; r < 4; r++) s[nj][r] = 0.f;

#pragma unroll
        for (int kk = 0; kk < 4; ++kk) {
            uint32_t kf[8][2];
#pragma unroll
            for (int p = 0; p < 4; p++) {
                uint32_t addr = st + (p * 16 + b_row) * FROWB + (kk * 16 + b_kh) * 2;
                ldm_x4(kf[2 * p][0], kf[2 * p][1], kf[2 * p + 1][0], kf[2 * p + 1][1], addr);
            }
#pragma unroll
            for (int nj = 0; nj < 8; nj++)
                mma_f16(s[nj][0], s[nj][1], s[nj][2], s[nj][3],
                        qf[kk][0], qf[kk][1], qf[kk][2], qf[kk][3], kf[nj][0], kf[nj][1]);
#pragma unroll
            for (int p = 0; p < 4; p++) {
                uint32_t addr = st + FARR + (p * 16 + b_row) * FROWB + (kk * 16 + b_kh) * 2;
                ldm_x4(kf[2 * p][0], kf[2 * p][1], kf[2 * p + 1][0], kf[2 * p + 1][1], addr);
            }
#pragma unroll
            for (int nj = 0; nj < 8; nj++)
                mma_f16(s[nj][0], s[nj][1], s[nj][2], s[nj][3],
                        qf[kk][0], qf[kk][1], qf[kk][2], qf[kk][3], kf[nj][0], kf[nj][1]);
        }

        // ---- scale + causal mask ----
#pragma unroll
        for (int nj = 0; nj < 8; nj++) {
#pragma unroll
            for (int r = 0; r < 4; r++) s[nj][r] *= 0.125f;
            if (kt == qt) {
                int col = kt * 64 + nj * 8 + tig * 2;
                if (col > row0g)     s[nj][0] = -1e30f;
                if (col + 1 > row0g) s[nj][1] = -1e30f;
                if (col > row0g + 8)     s[nj][2] = -1e30f;
                if (col + 1 > row0g + 8) s[nj][3] = -1e30f;
            }
        }

        // ---- online softmax ----
#pragma unroll
        for (int r = 0; r < 2; r++) {
            float rmax = -1e30f;
#pragma unroll
            for (int nj = 0; nj < 8; nj++)
                rmax = fmaxf(rmax, fmaxf(s[nj][2 * r], s[nj][2 * r + 1]));
            rmax = fmaxf(rmax, __shfl_xor_sync(0xffffffffu, rmax, 1));
            rmax = fmaxf(rmax, __shfl_xor_sync(0xffffffffu, rmax, 2));
            float mnew = fmaxf(m_[r], rmax);
            float alpha = __expf(m_[r] - mnew);
            float psum = 0.f;
#pragma unroll
            for (int nj = 0; nj < 8; nj++) {
                float p0 = __expf(s[nj][2 * r] - mnew);
                float p1 = __expf(s[nj][2 * r + 1] - mnew);
                s[nj][2 * r] = p0; s[nj][2 * r + 1] = p1;
                psum += p0 + p1;
            }
            psum += __shfl_xor_sync(0xffffffffu, psum, 1);
            psum += __shfl_xor_sync(0xffffffffu, psum, 2);
            l_[r] = l_[r] * alpha + psum;
            m_[r] = mnew;
#pragma unroll
            for (int nj = 0; nj < 8; nj++) {
                o[nj][2 * r] *= alpha;
                o[nj][2 * r + 1] *= alpha;
            }
        }

        // ---- O += P (Vh + Vl) ----
#pragma unroll
        for (int kk = 0; kk < 4; ++kk) {
            uint32_t pa[4] = {packh(s[2 * kk][0],     s[2 * kk][1]),
                              packh(s[2 * kk][2],     s[2 * kk][3]),
                              packh(s[2 * kk + 1][0], s[2 * kk + 1][1]),
                              packh(s[2 * kk + 1][2], s[2 * kk + 1][3])};
            uint32_t vf[8][2];
#pragma unroll
            for (int p = 0; p < 4; p++) {
                uint32_t addr = st + 2 * FARR + (kk * 16 + v_row) * FROWB + (p * 16 + v_col) * 2;
                ldm_x4_t(vf[2 * p][0], vf[2 * p][1], vf[2 * p + 1][0], vf[2 * p + 1][1], addr);
            }
#pragma unroll
            for (int nj = 0; nj < 8; nj++)
                mma_f16(o[nj][0], o[nj][1], o[nj][2], o[nj][3],
                        pa[0], pa[1], pa[2], pa[3], vf[nj][0], vf[nj][1]);
#pragma unroll
            for (int p = 0; p < 4; p++) {
                uint32_t addr = st + 3 * FARR + (kk * 16 + v_row) * FROWB + (p * 16 + v_col) * 2;
                ldm_x4_t(vf[2 * p][0], vf[2 * p][1], vf[2 * p + 1][0], vf[2 * p + 1][1], addr);
            }
#pragma unroll
            for (int nj = 0; nj < 8; nj++)
                mma_f16(o[nj][0], o[nj][1], o[nj][2], o[nj][3],
                        pa[0], pa[1], pa[2], pa[3], vf[nj][0], vf[nj][1]);
        }
        __syncthreads();
    }

    // ---- write O as single fp16 (A of proj) ----
    float inv0 = 1.f / l_[0], inv1 = 1.f / l_[1];
    int r0 = row0g, r1 = row0g + 8;
#pragma unroll
    for (int nj = 0; nj < 8; nj++) {
        int col = h * HDIM + nj * 8 + tig * 2;
        *(uint32_t*)(g_ao + ((size_t)(b * NTOK) + r0) * NCH + col)
            = packh(o[nj][0] * inv0, o[nj][1] * inv0);
        *(uint32_t*)(g_ao + ((size_t)(b * NTOK) + r1) * NCH + col)
            = packh(o[nj][2] * inv1, o[nj][3] * inv1);
    }
}

// --------------------------------- host ----------------------------------------
extern "C" void kernel_launch(void* const* d_in, const int* in_sizes, int n_in,
                              void* d_out, int out_size)
{
    const float *x = nullptr, *qkv_w = nullptr, *qkv_b = nullptr;
    const float *proj_w = nullptr, *proj_b = nullptr;
    const float *qn_w = nullptr, *qn_b = nullptr, *kn_w = nullptr, *kn_b = nullptr;
    const int *pos = nullptr, *tpos = nullptr;
    int n192 = 0;
    for (int i = 0; i < n_in; i++) {
        long sz = in_sizes[i];
        if (sz == (long)NB * NTOK * NCH && x == nullptr) x = (const float*)d_in[i];
        else if (sz == (long)NB * (NTOK - NSEG_T0)) pos = (const int*)d_in[i];
        else if (sz == (long)NB * NSEG_T0) tpos = (const int*)d_in[i];
        else if (sz == 3L * 3 * NCH * NCH) qkv_w = (const float*)d_in[i];
        else if (sz == 3L * 3 * NCH) qkv_b = (const float*)d_in[i];
        else if (sz == 3L * NCH * NCH) proj_w = (const float*)d_in[i];
        else if (sz == 3L * NCH) proj_b = (const float*)d_in[i];
        else if (sz == 3L * HDIM) {
            const float* p = (const float*)d_in[i];
            if (n192 == 0) qn_w = p; else if (n192 == 1) qn_b = p;
            else if (n192 == 2) kn_w = p; else kn_b = p;
            n192++;
        }
    }
    float* out = (float*)d_out;

    __half *p_xa, *p_wqh, *p_wql, *p_wph, *p_wpl;
    cudaGetSymbolAddress((void**)&p_xa, g_xa);
    cudaGetSymbolAddress((void**)&p_wqh, g_wqh);
    cudaGetSymbolAddress((void**)&p_wql, g_wql);
    cudaGetSymbolAddress((void**)&p_wph, g_wph);
    cudaGetSymbolAddress((void**)&p_wpl, g_wpl);

    cudaFuncSetAttribute(qkv_mma, cudaFuncAttributeMaxDynamicSharedMemorySize, GSMEM);
    cudaFuncSetAttribute(proj_mma, cudaFuncAttributeMaxDynamicSharedMemorySize, GSMEM);
    cudaFuncSetAttribute(flash_mma, cudaFuncAttributeMaxDynamicSharedMemorySize, FSMEM);

    // 0) converts + RoPE LUT
    cvt_half <<<512, 256>>>(x, p_xa, (long)NB * NTOK * NCH / 4);
    cvt_split<<<512, 256>>>(qkv_w, p_wqh, p_wql, 3L * 3 * NCH * NCH / 4);
    cvt_split<<<512, 256>>>(proj_w, p_wph, p_wpl, 3L * NCH * NCH / 4);
    build_rope_lut<<<(NB * NTOK * 32 + 255) / 256, 256>>>(pos, tpos);

    // 1) QKV projections with fused LN+RoPE+scatter epilogue
    qkv_mma<<<dim3(24, 34), 256, GSMEM>>>(qkv_b, qn_w, qn_b, kn_w, kn_b);

    // 2) flash attention (64-row q tiles, big tiles scheduled first)
    flash_mma<<<dim3(NTOK / 64, NH, NB), 128, FSMEM>>>();

    // 3) output projections
    proj_mma<<<dim3(8, 34), 256, GSMEM>>>(proj_b, out);
}

// round 14
// speedup vs baseline: 1.0095x; 1.0095x over previous
#include <cuda_runtime.h>
#include <cuda_fp16.h>
#include <cstdint>
#include <math.h>

#define NB   2
#define NTOK 2112
#define NCH  1024
#define NH   16
#define HDIM 64
#define NSEG_T0 64
#define NSEG_T1 1024

// ---------------- scratch (static device globals: no allocation) ----------------
__device__ __align__(16) __half g_xa [(size_t)NB * NTOK * NCH];
__device__ __align__(16) __half g_wqh[(size_t)3 * 3 * NCH * NCH];
__device__ __align__(16) __half g_wql[(size_t)3 * 3 * NCH * NCH];
__device__ __align__(16) __half g_wph[(size_t)3 * NCH * NCH];
__device__ __align__(16) __half g_wpl[(size_t)3 * NCH * NCH];
__device__ __align__(16) __half g_ao [(size_t)NB * NTOK * NCH];
__device__ __align__(16) __half g_qa[(size_t)NB * NH * NTOK * HDIM];
__device__ __align__(16) __half g_kh[(size_t)NB * NH * NTOK * HDIM];
__device__ __align__(16) __half g_kl[(size_t)NB * NH * NTOK * HDIM];
__device__ __align__(16) __half g_vh[(size_t)NB * NH * NTOK * HDIM];
__device__ __align__(16) __half g_vl[(size_t)NB * NH * NTOK * HDIM];
__device__ float g_ct[(size_t)NB * NTOK * 32];
__device__ float g_st[(size_t)NB * NTOK * 32];

// ---------------- PTX helpers ---------------------------------------------------
__device__ __forceinline__ uint32_t smem_u32(const void* p) {
    uint32_t a;
    asm("{ .reg .u64 t; cvta.to.shared.u64 t, %1; cvt.u32.u64 %0, t; }" : "=r"(a) : "l"(p));
    return a;
}
__device__ __forceinline__ void cp16(uint32_t dst, const void* src) {
    asm volatile("cp.async.cg.shared.global [%0], [%1], 16;" :: "r"(dst), "l"(src));
}
#define CP_COMMIT() asm volatile("cp.async.commit_group;" ::: "memory")
#define CP_WAIT(n)  asm volatile("cp.async.wait_group %0;" :: "n"(n) : "memory")

__device__ __forceinline__ void ldm_x4(uint32_t& r0, uint32_t& r1, uint32_t& r2, uint32_t& r3,
                                       uint32_t addr) {
    asm volatile("ldmatrix.sync.aligned.m8n8.x4.shared.b16 {%0,%1,%2,%3}, [%4];"
                 : "=r"(r0), "=r"(r1), "=r"(r2), "=r"(r3) : "r"(addr));
}
__device__ __forceinline__ void ldm_x4_t(uint32_t& r0, uint32_t& r1, uint32_t& r2, uint32_t& r3,
                                         uint32_t addr) {
    asm volatile("ldmatrix.sync.aligned.m8n8.x4.trans.shared.b16 {%0,%1,%2,%3}, [%4];"
                 : "=r"(r0), "=r"(r1), "=r"(r2), "=r"(r3) : "r"(addr));
}
__device__ __forceinline__ void mma_f16(float& c0, float& c1, float& c2, float& c3,
                                        uint32_t a0, uint32_t a1, uint32_t a2, uint32_t a3,
                                        uint32_t b0, uint32_t b1) {
    asm volatile(
        "mma.sync.aligned.m16n8k16.row.col.f32.f16.f16.f32 "
        "{%0,%1,%2,%3}, {%4,%5,%6,%7}, {%8,%9}, {%0,%1,%2,%3};"
        : "+f"(c0), "+f"(c1), "+f"(c2), "+f"(c3)
        : "r"(a0), "r"(a1), "r"(a2), "r"(a3), "r"(b0), "r"(b1));
}
__device__ __forceinline__ uint32_t packh(float lo, float hi) {
    __half2 h = __floats2half2_rn(lo, hi);
    return *(uint32_t*)&h;
}

// ------- row-tile mapping: 17 tiles per batch -------------------------------------
__device__ __forceinline__ void tile_map(int ty, int& seg, int& rowstart, int& rows)
{
    if (ty == 0)      { seg = 0; rowstart = 0;                     rows = 64;  }
    else if (ty < 9)  { seg = 1; rowstart = 64   + (ty - 1) * 128; rows = 128; }
    else              { seg = 2; rowstart = 1088 + (ty - 9) * 128; rows = 128; }
}

// ---------------- fp32 -> fp16 converts ------------------------------------------
__global__ void cvt_half(const float* __restrict__ src, __half* __restrict__ dst, long n4)
{
    long stride = (long)gridDim.x * blockDim.x;
    for (long i = blockIdx.x * (long)blockDim.x + threadIdx.x; i < n4; i += stride) {
        float4 v = *(const float4*)(src + i * 4);
        *(uint2*)(dst + i * 4) = make_uint2(packh(v.x, v.y), packh(v.z, v.w));
    }
}
__global__ void cvt_split(const float* __restrict__ src, __half* __restrict__ hi,
                          __half* __restrict__ lo, long n4)
{
    long stride = (long)gridDim.x * blockDim.x;
    for (long i = blockIdx.x * (long)blockDim.x + threadIdx.x; i < n4; i += stride) {
        float4 v = *(const float4*)(src + i * 4);
        float h0 = __half2float(__float2half_rn(v.x));
        float h1 = __half2float(__float2half_rn(v.y));
        float h2 = __half2float(__float2half_rn(v.z));
        float h3 = __half2float(__float2half_rn(v.w));
        *(uint2*)(hi + i * 4) = make_uint2(packh(h0, h1), packh(h2, h3));
        *(uint2*)(lo + i * 4) = make_uint2(packh(v.x - h0, v.y - h1),
                                           packh(v.z - h2, v.w - h3));
    }
}

// ---------------- RoPE LUT build (fp32 trig) --------------------------------------
__global__ void build_rope_lut(const int* __restrict__ pos_ids,
                               const int* __restrict__ tpos_ids)
{
    int idx = blockIdx.x * blockDim.x + threadIdx.x;
    if (idx >= NB * NTOK * 32) return;
    int dd = idx & 31;
    int t = (idx >> 5) % NTOK;
    int b = idx / (NTOK * 32);
    int pos = (t < NSEG_T0) ? tpos_ids[b * NSEG_T0 + t]
                            : pos_ids[b * (NTOK - NSEG_T0) + (t - NSEG_T0)];
    float inv = 1.0f / powf(10000.0f, (float)dd / 32.0f);
    float ang = (float)pos * inv;
    float s, c;
    sincosf(ang, &s, &c);
    g_ct[idx] = c;
    g_st[idx] = s;
}

// ---------------- warp-mma GEMM mainloop: 128x128, 256 thr, 2-stage ---------------
#define KTILE 64
#define NSTAGE (NCH / KTILE)          // 16
#define SROWB 144
#define ARR_BYTES (128 * SROWB)
#define STAGE_BYTES (3 * ARR_BYTES)   // A, Bh, Bl
#define GSMEM (2 * STAGE_BYTES)

__device__ __forceinline__ void load_stage(uint32_t sb,
                                           const __half* __restrict__ A,
                                           const __half* __restrict__ Bh,
                                           const __half* __restrict__ Bl,
                                           int k0, int Mrem)
{
    const int tid = threadIdx.x;
#pragma unroll
    for (int i = 0; i < 4; i++) {
        int idx = tid + i * 256;
        int row = idx >> 3;
        int c16 = idx & 7;
        int ar  = row < Mrem ? row : Mrem - 1;
        size_t aoff = (size_t)ar * NCH + k0 + c16 * 8;
        size_t boff = (size_t)row * NCH + k0 + c16 * 8;
        uint32_t d = sb + row * SROWB + c16 * 16;
        cp16(d,                 A  + aoff);
        cp16(d + ARR_BYTES,     Bh + boff);
        cp16(d + 2 * ARR_BYTES, Bl + boff);
    }
}

__device__ __forceinline__ void gemm_mainloop(const __half* __restrict__ A,
                                              const __half* __restrict__ Bh,
                                              const __half* __restrict__ Bl,
                                              int Mrem, float acc[2][8][4])
{
    extern __shared__ char dsm[];
    uint32_t sb = smem_u32(dsm);
    const int tid = threadIdx.x, wid = tid >> 5, lane = tid & 31;
    const int m0w = (wid & 3) * 32;
    const int n0w = (wid >> 2) * 64;

#pragma unroll
    for (int mi = 0; mi < 2; mi++)
#pragma unroll
        for (int nj = 0; nj < 8; nj++)
#pragma unroll
            for (int r = 0; r < 4; r++) acc[mi][nj][r] = 0.f;

    const int a_row = (lane & 15);
    const int a_kh  = (lane >> 4) << 3;
    const int b_row = (lane & 7) + ((lane >> 4) << 3);
    const int b_kh  = ((lane >> 3) & 1) << 3;

    load_stage(sb, A, Bh, Bl, 0, Mrem);
    CP_COMMIT();

    for (int s = 0; s < NSTAGE; ++s) {
        uint32_t cb = sb + (s & 1) * STAGE_BYTES;
        if (s + 1 < NSTAGE) {
            load_stage(sb + ((s + 1) & 1) * STAGE_BYTES, A, Bh, Bl, (s + 1) * KTILE, Mrem);
            CP_COMMIT();
            CP_WAIT(1);
        } else {
            CP_WAIT(0);
        }
        __syncthreads();

#pragma unroll
        for (int kk = 0; kk < 4; ++kk) {
            uint32_t af[2][4], bh[8][2], bl[8][2];
#pragma unroll
            for (int mi = 0; mi < 2; mi++) {
                uint32_t addr = cb + (m0w + mi * 16 + a_row) * SROWB + (kk * 16 + a_kh) * 2;
                ldm_x4(af[mi][0], af[mi][1], af[mi][2], af[mi][3], addr);
            }
#pragma unroll
            for (int p = 0; p < 4; p++) {
                uint32_t addr = cb + ARR_BYTES
                              + (n0w + p * 16 + b_row) * SROWB + (kk * 16 + b_kh) * 2;
                ldm_x4(bh[2 * p][0], bh[2 * p][1], bh[2 * p + 1][0], bh[2 * p + 1][1], addr);
                ldm_x4(bl[2 * p][0], bl[2 * p][1], bl[2 * p + 1][0], bl[2 * p + 1][1],
                       addr + ARR_BYTES);
            }
#pragma unroll
            for (int mi = 0; mi < 2; mi++)
#pragma unroll
                for (int nj = 0; nj < 8; nj++) {
                    float* c = acc[mi][nj];
                    mma_f16(c[0], c[1], c[2], c[3],
                            af[mi][0], af[mi][1], af[mi][2], af[mi][3],
                            bh[nj][0], bh[nj][1]);
                    mma_f16(c[0], c[1], c[2], c[3],
                            af[mi][0], af[mi][1], af[mi][2], af[mi][3],
                            bl[nj][0], bl[nj][1]);
                }
        }
        __syncthreads();
    }
}

// ---------------- QKV GEMM + fused LN/RoPE/scatter epilogue ----------------------
__global__ __launch_bounds__(256, 1) void qkv_mma(const float* __restrict__ qkv_b,
                                                  const float* __restrict__ qn_w,
                                                  const float* __restrict__ qn_b,
                                                  const float* __restrict__ kn_w,
                                                  const float* __restrict__ kn_b)
{
    int y = blockIdx.y;
    int b = y / 17, t17 = y % 17;
    int seg, rowstart, rows;
    tile_map(t17, seg, rowstart, rows);
    int n0 = blockIdx.x * 128;
    size_t arow = (size_t)(b * NTOK + rowstart) * NCH;
    size_t brow = (size_t)(seg * 3 * NCH + n0) * NCH;

    float acc[2][8][4];
    gemm_mainloop(g_xa + arow, g_wqh + brow, g_wql + brow, rows, acc);

    const int tid = threadIdx.x, wid = tid >> 5, lane = tid & 31;
    const int m0w = (wid & 3) * 32;
    const int n0w = (wid >> 2) * 64;
    const int grp = lane >> 2, tig = lane & 3;

    const int gn = n0 + n0w;
    const int part = gn >> 10;            // 0=q, 1=k, 2=v
    const int hd = (gn & 1023) >> 6;
    const float* bias = qkv_b + seg * 3 * NCH + gn;
    const float* wln = (part == 0) ? qn_w + seg * 64 : kn_w + seg * 64;
    const float* bln = (part == 0) ? qn_b + seg * 64 : kn_b + seg * 64;

#pragma unroll
    for (int mi = 0; mi < 2; mi++) {
#pragma unroll
        for (int r = 0; r < 2; r++) {
            int row = m0w + mi * 16 + grp + r * 8;
            bool valid = row < rows;
            int t = rowstart + row;
            size_t ob = ((size_t)(b * NH + hd) * NTOK + t) * HDIM;

            float yv[8][2];
#pragma unroll
            for (int nj = 0; nj < 8; nj++) {
                int d = nj * 8 + tig * 2;
                yv[nj][0] = acc[mi][nj][2 * r]     + bias[d];
                yv[nj][1] = acc[mi][nj][2 * r + 1] + bias[d + 1];
            }

            if (part == 2) {
                if (valid) {
#pragma unroll
                    for (int nj = 0; nj < 8; nj++) {
                        int d = nj * 8 + tig * 2;
                        float v0 = yv[nj][0], v1 = yv[nj][1];
                        float h0 = __half2float(__float2half_rn(v0));
                        float h1 = __half2float(__float2half_rn(v1));
                        *(uint32_t*)(g_vh + ob + d) = packh(v0, v1);
                        *(uint32_t*)(g_vl + ob + d) = packh(v0 - h0, v1 - h1);
                    }
                }
            } else {
                float s = 0.f;
#pragma unroll
                for (int nj = 0; nj < 8; nj++) s += yv[nj][0] + yv[nj][1];
                s += __shfl_xor_sync(0xffffffffu, s, 1);
                s += __shfl_xor_sync(0xffffffffu, s, 2);
                float mu = s * (1.f / 64.f);
                float s2 = 0.f;
#pragma unroll
                for (int nj = 0; nj < 8; nj++) {
                    float d0 = yv[nj][0] - mu, d1 = yv[nj][1] - mu;
                    s2 += d0 * d0 + d1 * d1;
                }
                s2 += __shfl_xor_sync(0xffffffffu, s2, 1);
                s2 += __shfl_xor_sync(0xffffffffu, s2, 2);
                float istd = rsqrtf(s2 * (1.f / 64.f) + 1e-5f);
#pragma unroll
                for (int nj = 0; nj < 8; nj++) {
                    int d = nj * 8 + tig * 2;
                    yv[nj][0] = (yv[nj][0] - mu) * istd * wln[d]     + bln[d];
                    yv[nj][1] = (yv[nj][1] - mu) * istd * wln[d + 1] + bln[d + 1];
                }
                const float* ctp = g_ct + ((size_t)(b * NTOK) + t) * 32;
                const float* stp = g_st + ((size_t)(b * NTOK) + t) * 32;
#pragma unroll
                for (int nj = 0; nj < 4; nj++) {
                    int d = nj * 8 + tig * 2;
                    float cs0 = ctp[d], sn0 = stp[d];
                    float cs1 = ctp[d + 1], sn1 = stp[d + 1];
                    float a0 = yv[nj][0], a1 = yv[nj][1];
                    float b0 = yv[nj + 4][0], b1 = yv[nj + 4][1];
                    yv[nj][0]     = a0 * cs0 - b0 * sn0;
                    yv[nj][1]     = a1 * cs1 - b1 * sn1;
                    yv[nj + 4][0] = b0 * cs0 + a0 * sn0;
                    yv[nj + 4][1] = b1 * cs1 + a1 * sn1;
                }
                if (valid) {
                    if (part == 0) {
#pragma unroll
                        for (int nj = 0; nj < 8; nj++) {
                            int d = nj * 8 + tig * 2;
                            *(uint32_t*)(g_qa + ob + d) = packh(yv[nj][0], yv[nj][1]);
                        }
                    } else {
#pragma unroll
                        for (int nj = 0; nj < 8; nj++) {
                            int d = nj * 8 + tig * 2;
                            float v0 = yv[nj][0], v1 = yv[nj][1];
                            float h0 = __half2float(__float2half_rn(v0));
                            float h1 = __half2float(__float2half_rn(v1));
                            *(uint32_t*)(g_kh + ob + d) = packh(v0, v1);
                            *(uint32_t*)(g_kl + ob + d) = packh(v0 - h0, v1 - h1);
                        }
                    }
                }
            }
        }
    }
}

// ---------------- proj GEMM (fp32 bias epilogue) ----------------------------------
__global__ __launch_bounds__(256, 1) void proj_mma(const float* __restrict__ proj_b,
                                                   float* __restrict__ out)
{
    int y = blockIdx.y;
    int b = y / 17, t17 = y % 17;
    int seg, rowstart, rows;
    tile_map(t17, seg, rowstart, rows);
    int n0 = blockIdx.x * 128;
    size_t arow = (size_t)(b * NTOK + rowstart) * NCH;
    size_t brow = (size_t)(seg * NCH + n0) * NCH;

    float acc[2][8][4];
    gemm_mainloop(g_ao + arow, g_wph + brow, g_wpl + brow, rows, acc);

    const int tid = threadIdx.x, wid = tid >> 5, lane = tid & 31;
    const int m0w = (wid & 3) * 32;
    const int n0w = (wid >> 2) * 64;
    const int grp = lane >> 2, tig = lane & 3;
    const float* bias = proj_b + seg * NCH + n0;
    float* Cout = out + (size_t)(b * NTOK + rowstart) * NCH + n0;

#pragma unroll
    for (int mi = 0; mi < 2; mi++) {
        int r0 = m0w + mi * 16 + grp;
        int r1 = r0 + 8;
#pragma unroll
        for (int nj = 0; nj < 8; nj++) {
            int n = n0w + nj * 8 + tig * 2;
            float b0 = bias[n], b1 = bias[n + 1];
            if (r0 < rows) {
                float2 v = make_float2(acc[mi][nj][0] + b0, acc[mi][nj][1] + b1);
                *(float2*)(Cout + (size_t)r0 * NCH + n) = v;
            }
            if (r1 < rows) {
                float2 v = make_float2(acc[mi][nj][2] + b0, acc[mi][nj][3] + b1);
                *(float2*)(Cout + (size_t)r1 * NCH + n) = v;
            }
        }
    }
}

// ---------------- flash attention: 64-q tiles, 128 thr, desc schedule ------------
#define FROWB 144
#define FARR  (64 * FROWB)          // 9216
#define FSMEM (9 * FARR)            // 82944

__device__ __forceinline__ void load_kv_stage(uint32_t dst, size_t hb, int t0)
{
    const int tid = threadIdx.x;
#pragma unroll
    for (int i = 0; i < 4; i++) {
        int idx = tid + i * 128;
        int row = idx >> 3;
        int c16 = idx & 7;
        size_t off = hb + (size_t)(t0 + row) * HDIM + c16 * 8;
        uint32_t d = dst + row * FROWB + c16 * 16;
        cp16(d,            g_kh + off);
        cp16(d + FARR,     g_kl + off);
        cp16(d + 2 * FARR, g_vh + off);
        cp16(d + 3 * FARR, g_vl + off);
    }
}

__global__ __launch_bounds__(128, 2) void flash_mma()
{
    extern __shared__ char fsm[];
    uint32_t sb = smem_u32(fsm);
    const uint32_t Qs = sb;
    const uint32_t KV = sb + FARR;

    const int qt = (gridDim.x - 1) - blockIdx.x;   // big tiles first
    const int h = blockIdx.y, b = blockIdx.z;
    const int q0 = qt * 64;
    const int tid = threadIdx.x, wid = tid >> 5, lane = tid & 31;
    const size_t hb = ((size_t)(b * NH + h)) * NTOK * HDIM;

#pragma unroll
    for (int i = 0; i < 4; i++) {
        int idx = tid + i * 128;
        int row = idx >> 3;
        int c16 = idx & 7;
        size_t off = hb + (size_t)(q0 + row) * HDIM + c16 * 8;
        if (idx < 512)
            cp16(Qs + row * FROWB + c16 * 16, g_qa + off);
    }
    CP_COMMIT();
    load_kv_stage(KV, hb, 0);
    CP_COMMIT();
    CP_WAIT(1);
    __syncthreads();

    const int a_row = lane & 15;
    const int a_kh  = (lane >> 4) << 3;
    uint32_t qf[4][4];
#pragma unroll
    for (int kk = 0; kk < 4; kk++) {
        uint32_t addr = Qs + (wid * 16 + a_row) * FROWB + (kk * 16 + a_kh) * 2;
        ldm_x4(qf[kk][0], qf[kk][1], qf[kk][2], qf[kk][3], addr);
    }

    const int grp = lane >> 2, tig = lane & 3;
    const int b_row = (lane & 7) + ((lane >> 4) << 3);
    const int b_kh  = ((lane >> 3) & 1) << 3;
    const int v_row = (lane & 7) + (((lane >> 3) & 1) << 3);
    const int v_col = (lane >> 4) << 3;
    const int row0g = q0 + wid * 16 + grp;

    float m_[2] = {-1e30f, -1e30f}, l_[2] = {0.f, 0.f};
    float o[8][4];
#pragma unroll
    for (int nj = 0; nj < 8; nj++)
#pragma unroll
        for (int r = 0; r < 4; r++) o[nj][r] = 0.f;

    for (int kt = 0; kt <= qt; ++kt) {
        uint32_t st = KV + (kt & 1) * 4 * FARR;
        if (kt < qt) {
            load_kv_stage(KV + ((kt + 1) & 1) * 4 * FARR, hb, (kt + 1) * 64);
            CP_COMMIT();
            CP_WAIT(1);
        } else {
            CP_WAIT(0);
        }
        __syncthreads();

        float s[8][4];
#pragma unroll
        for (int nj = 0; nj < 8; nj++)
#pragma unroll
            for (int r = 0; r < 4; r++) s[nj][r] = 0.f;

#pragma unroll
        for (int kk = 0; kk < 4; ++kk) {
            uint32_t kf[8][2];
#pragma unroll
            for (int p = 0; p < 4; p++) {
                uint32_t addr = st + (p * 16 + b_row) * FROWB + (kk * 16 + b_kh) * 2;
                ldm_x4(kf[2 * p][0], kf[2 * p][1], kf[2 * p + 1][0], kf[2 * p + 1][1], addr);
            }
#pragma unroll
            for (int nj = 0; nj < 8; nj++)
                mma_f16(s[nj][0], s[nj][1], s[nj][2], s[nj][3],
                        qf[kk][0], qf[kk][1], qf[kk][2], qf[kk][3], kf[nj][0], kf[nj][1]);
#pragma unroll
            for (int p = 0; p < 4; p++) {
                uint32_t addr = st + FARR + (p * 16 + b_row) * FROWB + (kk * 16 + b_kh) * 2;
                ldm_x4(kf[2 * p][0], kf[2 * p][1], kf[2 * p + 1][0], kf[2 * p + 1][1], addr);
            }
#pragma unroll
            for (int nj = 0; nj < 8; nj++)
                mma_f16(s[nj][0], s[nj][1], s[nj][2], s[nj][3],
                        qf[kk][0], qf[kk][1], qf[kk][2], qf[kk][3], kf[nj][0], kf[nj][1]);
        }

#pragma unroll
        for (int nj = 0; nj < 8; nj++) {
#pragma unroll
            for (int r = 0; r < 4; r++) s[nj][r] *= 0.125f;
            if (kt == qt) {
                int col = kt * 64 + nj * 8 + tig * 2;
                if (col > row0g)     s[nj][0] = -1e30f;
                if (col + 1 > row0g) s[nj][1] = -1e30f;
                if (col > row0g + 8)     s[nj][2] = -1e30f;
                if (col + 1 > row0g + 8) s[nj][3] = -1e30f;
            }
        }

#pragma unroll
        for (int r = 0; r < 2; r++) {
            float rmax = -1e30f;
#pragma unroll
            for (int nj = 0; nj < 8; nj++)
                rmax = fmaxf(rmax, fmaxf(s[nj][2 * r], s[nj][2 * r + 1]));
            rmax = fmaxf(rmax, __shfl_xor_sync(0xffffffffu, rmax, 1));
            rmax = fmaxf(rmax, __shfl_xor_sync(0xffffffffu, rmax, 2));
            float mnew = fmaxf(m_[r], rmax);
            float alpha = __expf(m_[r] - mnew);
            float psum = 0.f;
#pragma unroll
            for (int nj = 0; nj < 8; nj++) {
                float p0 = __expf(s[nj][2 * r] - mnew);
                float p1 = __expf(s[nj][2 * r + 1] - mnew);
                s[nj][2 * r] = p0; s[nj][2 * r + 1] = p1;
                psum += p0 + p1;
            }
            psum += __shfl_xor_sync(0xffffffffu, psum, 1);
            psum += __shfl_xor_sync(0xffffffffu, psum, 2);
            l_[r] = l_[r] * alpha + psum;
            m_[r] = mnew;
#pragma unroll
            for (int nj = 0; nj < 8; nj++) {
                o[nj][2 * r] *= alpha;
                o[nj][2 * r + 1] *= alpha;
            }
        }

#pragma unroll
        for (int kk = 0; kk < 4; ++kk) {
            uint32_t pa[4] = {packh(s[2 * kk][0],     s[2 * kk][1]),
                              packh(s[2 * kk][2],     s[2 * kk][3]),
                              packh(s[2 * kk + 1][0], s[2 * kk + 1][1]),
                              packh(s[2 * kk + 1][2], s[2 * kk + 1][3])};
            uint32_t vf[8][2];
#pragma unroll
            for (int p = 0; p < 4; p++) {
                uint32_t addr = st + 2 * FARR + (kk * 16 + v_row) * FROWB + (p * 16 + v_col) * 2;
                ldm_x4_t(vf[2 * p][0], vf[2 * p][1], vf[2 * p + 1][0], vf[2 * p + 1][1], addr);
            }
#pragma unroll
            for (int nj = 0; nj < 8; nj++)
                mma_f16(o[nj][0], o[nj][1], o[nj][2], o[nj][3],
                        pa[0], pa[1], pa[2], pa[3], vf[nj][0], vf[nj][1]);
#pragma unroll
            for (int p = 0; p < 4; p++) {
                uint32_t addr = st + 3 * FARR + (kk * 16 + v_row) * FROWB + (p * 16 + v_col) * 2;
                ldm_x4_t(vf[2 * p][0], vf[2 * p][1], vf[2 * p + 1][0], vf[2 * p + 1][1], addr);
            }
#pragma unroll
            for (int nj = 0; nj < 8; nj++)
                mma_f16(o[nj][0], o[nj][1], o[nj][2], o[nj][3],
                        pa[0], pa[1], pa[2], pa[3], vf[nj][0], vf[nj][1]);
        }
        __syncthreads();
    }

    float inv0 = 1.f / l_[0], inv1 = 1.f / l_[1];
    int r0 = row0g, r1 = row0g + 8;
#pragma unroll
    for (int nj = 0; nj < 8; nj++) {
        int col = h * HDIM + nj * 8 + tig * 2;
        *(uint32_t*)(g_ao + ((size_t)(b * NTOK) + r0) * NCH + col)
            = packh(o[nj][0] * inv0, o[nj][1] * inv0);
        *(uint32_t*)(g_ao + ((size_t)(b * NTOK) + r1) * NCH + col)
            = packh(o[nj][2] * inv1, o[nj][3] * inv1);
    }
}

// --------------------------------- host ----------------------------------------
extern "C" void kernel_launch(void* const* d_in, const int* in_sizes, int n_in,
                              void* d_out, int out_size)
{
    const float *x = nullptr, *qkv_w = nullptr, *qkv_b = nullptr;
    const float *proj_w = nullptr, *proj_b = nullptr;
    const float *qn_w = nullptr, *qn_b = nullptr, *kn_w = nullptr, *kn_b = nullptr;
    const int *pos = nullptr, *tpos = nullptr;
    int n192 = 0;
    for (int i = 0; i < n_in; i++) {
        long sz = in_sizes[i];
        if (sz == (long)NB * NTOK * NCH && x == nullptr) x = (const float*)d_in[i];
        else if (sz == (long)NB * (NTOK - NSEG_T0)) pos = (const int*)d_in[i];
        else if (sz == (long)NB * NSEG_T0) tpos = (const int*)d_in[i];
        else if (sz == 3L * 3 * NCH * NCH) qkv_w = (const float*)d_in[i];
        else if (sz == 3L * 3 * NCH) qkv_b = (const float*)d_in[i];
        else if (sz == 3L * NCH * NCH) proj_w = (const float*)d_in[i];
        else if (sz == 3L * NCH) proj_b = (const float*)d_in[i];
        else if (sz == 3L * HDIM) {
            const float* p = (const float*)d_in[i];
            if (n192 == 0) qn_w = p; else if (n192 == 1) qn_b = p;
            else if (n192 == 2) kn_w = p; else kn_b = p;
            n192++;
        }
    }
    float* out = (float*)d_out;

    __half *p_xa, *p_wqh, *p_wql, *p_wph, *p_wpl;
    cudaGetSymbolAddress((void**)&p_xa, g_xa);
    cudaGetSymbolAddress((void**)&p_wqh, g_wqh);
    cudaGetSymbolAddress((void**)&p_wql, g_wql);
    cudaGetSymbolAddress((void**)&p_wph, g_wph);
    cudaGetSymbolAddress((void**)&p_wpl, g_wpl);

    cudaFuncSetAttribute(qkv_mma, cudaFuncAttributeMaxDynamicSharedMemorySize, GSMEM);
    cudaFuncSetAttribute(proj_mma, cudaFuncAttributeMaxDynamicSharedMemorySize, GSMEM);
    cudaFuncSetAttribute(flash_mma, cudaFuncAttributeMaxDynamicSharedMemorySize, FSMEM);

    // stream fork/join: s0 = capture (main) stream; s1, s2 = side branches.
    // Legal under graph capture via event fork/join.
    static cudaStream_t s1 = nullptr, s2 = nullptr;
    static cudaEvent_t e_fork = nullptr, e_w1 = nullptr, e_lut = nullptr, e_wp = nullptr;
    if (!s1) {
        cudaStreamCreateWithFlags(&s1, cudaStreamNonBlocking);
        cudaStreamCreateWithFlags(&s2, cudaStreamNonBlocking);
        cudaEventCreateWithFlags(&e_fork, cudaEventDisableTiming);
        cudaEventCreateWithFlags(&e_w1, cudaEventDisableTiming);
        cudaEventCreateWithFlags(&e_lut, cudaEventDisableTiming);
        cudaEventCreateWithFlags(&e_wp, cudaEventDisableTiming);
    }

    cudaStream_t s0 = 0;   // capture stream (default)
    cudaEventRecord(e_fork, s0);
    cudaStreamWaitEvent(s1, e_fork, 0);
    cudaStreamWaitEvent(s2, e_fork, 0);

    // s0: x convert (needed by qkv)
    cvt_half <<<512, 256, 0, s0>>>(x, p_xa, (long)NB * NTOK * NCH / 4);
    // s1: qkv weights + RoPE LUT (both needed by qkv)
    cvt_split<<<512, 256, 0, s1>>>(qkv_w, p_wqh, p_wql, 3L * 3 * NCH * NCH / 4);
    build_rope_lut<<<(NB * NTOK * 32 + 255) / 256, 256, 0, s1>>>(pos, tpos);
    cudaEventRecord(e_w1, s1);
    // s2: proj weights (needed only by proj — hides under qkv+flash)
    cvt_split<<<256, 256, 0, s2>>>(proj_w, p_wph, p_wpl, 3L * NCH * NCH / 4);
    cudaEventRecord(e_wp, s2);

    // join for qkv
    cudaStreamWaitEvent(s0, e_w1, 0);
    qkv_mma<<<dim3(24, 34), 256, GSMEM, s0>>>(qkv_b, qn_w, qn_b, kn_w, kn_b);

    // flash attention
    flash_mma<<<dim3(NTOK / 64, NH, NB), 128, FSMEM, s0>>>();

    // join for proj
    cudaStreamWaitEvent(s0, e_wp, 0);
    proj_mma<<<dim3(8, 34), 256, GSMEM, s0>>>(proj_b, out);
}

// round 15
// speedup vs baseline: 1.1196x; 1.1090x over previous
#include <cuda_runtime.h>
#include <cuda_fp16.h>
#include <cstdint>
#include <math.h>

#define NB   2
#define NTOK 2112
#define NCH  1024
#define NH   16
#define HDIM 64
#define NSEG_T0 64
#define NSEG_T1 1024

// ---------------- scratch (static device globals: no allocation) ----------------
__device__ __align__(16) __half g_xa [(size_t)NB * NTOK * NCH];
__device__ __align__(16) __half g_wqh[(size_t)3 * 3 * NCH * NCH];
__device__ __align__(16) __half g_wql[(size_t)3 * 3 * NCH * NCH];
__device__ __align__(16) __half g_wph[(size_t)3 * NCH * NCH];
__device__ __align__(16) __half g_wpl[(size_t)3 * NCH * NCH];
__device__ __align__(16) __half g_ao [(size_t)NB * NTOK * NCH];
__device__ __align__(16) __half g_qa[(size_t)NB * NH * NTOK * HDIM];
__device__ __align__(16) __half g_kh[(size_t)NB * NH * NTOK * HDIM];
__device__ __align__(16) __half g_kl[(size_t)NB * NH * NTOK * HDIM];
__device__ __align__(16) __half g_vh[(size_t)NB * NH * NTOK * HDIM];
__device__ __align__(16) __half g_vl[(size_t)NB * NH * NTOK * HDIM];
__device__ float g_ct[(size_t)NB * NTOK * 32];
__device__ float g_st[(size_t)NB * NTOK * 32];

// ---------------- PTX helpers ---------------------------------------------------
__device__ __forceinline__ uint32_t smem_u32(const void* p) {
    uint32_t a;
    asm("{ .reg .u64 t; cvta.to.shared.u64 t, %1; cvt.u32.u64 %0, t; }" : "=r"(a) : "l"(p));
    return a;
}
__device__ __forceinline__ void cp16(uint32_t dst, const void* src) {
    asm volatile("cp.async.cg.shared.global [%0], [%1], 16;" :: "r"(dst), "l"(src));
}
#define CP_COMMIT() asm volatile("cp.async.commit_group;" ::: "memory")
#define CP_WAIT(n)  asm volatile("cp.async.wait_group %0;" :: "n"(n) : "memory")

__device__ __forceinline__ void ldm_x4(uint32_t& r0, uint32_t& r1, uint32_t& r2, uint32_t& r3,
                                       uint32_t addr) {
    asm volatile("ldmatrix.sync.aligned.m8n8.x4.shared.b16 {%0,%1,%2,%3}, [%4];"
                 : "=r"(r0), "=r"(r1), "=r"(r2), "=r"(r3) : "r"(addr));
}
__device__ __forceinline__ void ldm_x4_t(uint32_t& r0, uint32_t& r1, uint32_t& r2, uint32_t& r3,
                                         uint32_t addr) {
    asm volatile("ldmatrix.sync.aligned.m8n8.x4.trans.shared.b16 {%0,%1,%2,%3}, [%4];"
                 : "=r"(r0), "=r"(r1), "=r"(r2), "=r"(r3) : "r"(addr));
}
__device__ __forceinline__ void mma_f16(float& c0, float& c1, float& c2, float& c3,
                                        uint32_t a0, uint32_t a1, uint32_t a2, uint32_t a3,
                                        uint32_t b0, uint32_t b1) {
    asm volatile(
        "mma.sync.aligned.m16n8k16.row.col.f32.f16.f16.f32 "
        "{%0,%1,%2,%3}, {%4,%5,%6,%7}, {%8,%9}, {%0,%1,%2,%3};"
        : "+f"(c0), "+f"(c1), "+f"(c2), "+f"(c3)
        : "r"(a0), "r"(a1), "r"(a2), "r"(a3), "r"(b0), "r"(b1));
}
__device__ __forceinline__ uint32_t packh(float lo, float hi) {
    __half2 h = __floats2half2_rn(lo, hi);
    return *(uint32_t*)&h;
}

// ------- row-tile mapping: 17 tiles per batch -------------------------------------
__device__ __forceinline__ void tile_map(int ty, int& seg, int& rowstart, int& rows)
{
    if (ty == 0)      { seg = 0; rowstart = 0;                     rows = 64;  }
    else if (ty < 9)  { seg = 1; rowstart = 64   + (ty - 1) * 128; rows = 128; }
    else              { seg = 2; rowstart = 1088 + (ty - 9) * 128; rows = 128; }
}

// ---------------- fp32 -> fp16 converts ------------------------------------------
__global__ void cvt_half(const float* __restrict__ src, __half* __restrict__ dst, long n4)
{
    long stride = (long)gridDim.x * blockDim.x;
    for (long i = blockIdx.x * (long)blockDim.x + threadIdx.x; i < n4; i += stride) {
        float4 v = *(const float4*)(src + i * 4);
        *(uint2*)(dst + i * 4) = make_uint2(packh(v.x, v.y), packh(v.z, v.w));
    }
}
__global__ void cvt_split(const float* __restrict__ src, __half* __restrict__ hi,
                          __half* __restrict__ lo, long n4)
{
    long stride = (long)gridDim.x * blockDim.x;
    for (long i = blockIdx.x * (long)blockDim.x + threadIdx.x; i < n4; i += stride) {
        float4 v = *(const float4*)(src + i * 4);
        float h0 = __half2float(__float2half_rn(v.x));
        float h1 = __half2float(__float2half_rn(v.y));
        float h2 = __half2float(__float2half_rn(v.z));
        float h3 = __half2float(__float2half_rn(v.w));
        *(uint2*)(hi + i * 4) = make_uint2(packh(h0, h1), packh(h2, h3));
        *(uint2*)(lo + i * 4) = make_uint2(packh(v.x - h0, v.y - h1),
                                           packh(v.z - h2, v.w - h3));
    }
}

// ---------------- RoPE LUT build (fp32 trig) --------------------------------------
__global__ void build_rope_lut(const int* __restrict__ pos_ids,
                               const int* __restrict__ tpos_ids)
{
    int idx = blockIdx.x * blockDim.x + threadIdx.x;
    if (idx >= NB * NTOK * 32) return;
    int dd = idx & 31;
    int t = (idx >> 5) % NTOK;
    int b = idx / (NTOK * 32);
    int pos = (t < NSEG_T0) ? tpos_ids[b * NSEG_T0 + t]
                            : pos_ids[b * (NTOK - NSEG_T0) + (t - NSEG_T0)];
    float inv = 1.0f / powf(10000.0f, (float)dd / 32.0f);
    float ang = (float)pos * inv;
    float s, c;
    sincosf(ang, &s, &c);
    g_ct[idx] = c;
    g_st[idx] = s;
}

// ---------------- warp-mma GEMM mainloop: 128x128, 256 thr, 2-stage ---------------
#define KTILE 64
#define NSTAGE (NCH / KTILE)          // 16
#define SROWB 144
#define ARR_BYTES (128 * SROWB)
#define STAGE_BYTES (3 * ARR_BYTES)   // A, Bh, Bl
#define GSMEM (2 * STAGE_BYTES)

__device__ __forceinline__ void load_stage(uint32_t sb,
                                           const __half* __restrict__ A,
                                           const __half* __restrict__ Bh,
                                           const __half* __restrict__ Bl,
                                           int k0, int Mrem)
{
    const int tid = threadIdx.x;
#pragma unroll
    for (int i = 0; i < 4; i++) {
        int idx = tid + i * 256;
        int row = idx >> 3;
        int c16 = idx & 7;
        int ar  = row < Mrem ? row : Mrem - 1;
        size_t aoff = (size_t)ar * NCH + k0 + c16 * 8;
        size_t boff = (size_t)row * NCH + k0 + c16 * 8;
        uint32_t d = sb + row * SROWB + c16 * 16;
        cp16(d,                 A  + aoff);
        cp16(d + ARR_BYTES,     Bh + boff);
        cp16(d + 2 * ARR_BYTES, Bl + boff);
    }
}

__device__ __forceinline__ void gemm_mainloop(const __half* __restrict__ A,
                                              const __half* __restrict__ Bh,
                                              const __half* __restrict__ Bl,
                                              int Mrem, float acc[2][8][4])
{
    extern __shared__ char dsm[];
    uint32_t sb = smem_u32(dsm);
    const int tid = threadIdx.x, wid = tid >> 5, lane = tid & 31;
    const int m0w = (wid & 3) * 32;
    const int n0w = (wid >> 2) * 64;

#pragma unroll
    for (int mi = 0; mi < 2; mi++)
#pragma unroll
        for (int nj = 0; nj < 8; nj++)
#pragma unroll
            for (int r = 0; r < 4; r++) acc[mi][nj][r] = 0.f;

    const int a_row = (lane & 15);
    const int a_kh  = (lane >> 4) << 3;
    const int b_row = (lane & 7) + ((lane >> 4) << 3);
    const int b_kh  = ((lane >> 3) & 1) << 3;

    load_stage(sb, A, Bh, Bl, 0, Mrem);
    CP_COMMIT();

    for (int s = 0; s < NSTAGE; ++s) {
        uint32_t cb = sb + (s & 1) * STAGE_BYTES;
        if (s + 1 < NSTAGE) {
            load_stage(sb + ((s + 1) & 1) * STAGE_BYTES, A, Bh, Bl, (s + 1) * KTILE, Mrem);
            CP_COMMIT();
            CP_WAIT(1);
        } else {
            CP_WAIT(0);
        }
        __syncthreads();

#pragma unroll
        for (int kk = 0; kk < 4; ++kk) {
            uint32_t af[2][4], bh[8][2], bl[8][2];
#pragma unroll
            for (int mi = 0; mi < 2; mi++) {
                uint32_t addr = cb + (m0w + mi * 16 + a_row) * SROWB + (kk * 16 + a_kh) * 2;
                ldm_x4(af[mi][0], af[mi][1], af[mi][2], af[mi][3], addr);
            }
#pragma unroll
            for (int p = 0; p < 4; p++) {
                uint32_t addr = cb + ARR_BYTES
                              + (n0w + p * 16 + b_row) * SROWB + (kk * 16 + b_kh) * 2;
                ldm_x4(bh[2 * p][0], bh[2 * p][1], bh[2 * p + 1][0], bh[2 * p + 1][1], addr);
                ldm_x4(bl[2 * p][0], bl[2 * p][1], bl[2 * p + 1][0], bl[2 * p + 1][1],
                       addr + ARR_BYTES);
            }
#pragma unroll
            for (int mi = 0; mi < 2; mi++)
#pragma unroll
                for (int nj = 0; nj < 8; nj++) {
                    float* c = acc[mi][nj];
                    mma_f16(c[0], c[1], c[2], c[3],
                            af[mi][0], af[mi][1], af[mi][2], af[mi][3],
                            bh[nj][0], bh[nj][1]);
                    mma_f16(c[0], c[1], c[2], c[3],
                            af[mi][0], af[mi][1], af[mi][2], af[mi][3],
                            bl[nj][0], bl[nj][1]);
                }
        }
        __syncthreads();
    }
}

// ---------------- QKV GEMM + fused LN/RoPE/scatter epilogue (per batch) ----------
__global__ __launch_bounds__(256, 1) void qkv_mma(int b,
                                                  const float* __restrict__ qkv_b,
                                                  const float* __restrict__ qn_w,
                                                  const float* __restrict__ qn_b,
                                                  const float* __restrict__ kn_w,
                                                  const float* __restrict__ kn_b)
{
    int t17 = blockIdx.y;
    int seg, rowstart, rows;
    tile_map(t17, seg, rowstart, rows);
    int n0 = blockIdx.x * 128;
    size_t arow = (size_t)(b * NTOK + rowstart) * NCH;
    size_t brow = (size_t)(seg * 3 * NCH + n0) * NCH;

    float acc[2][8][4];
    gemm_mainloop(g_xa + arow, g_wqh + brow, g_wql + brow, rows, acc);

    const int tid = threadIdx.x, wid = tid >> 5, lane = tid & 31;
    const int m0w = (wid & 3) * 32;
    const int n0w = (wid >> 2) * 64;
    const int grp = lane >> 2, tig = lane & 3;

    const int gn = n0 + n0w;
    const int part = gn >> 10;            // 0=q, 1=k, 2=v
    const int hd = (gn & 1023) >> 6;
    const float* bias = qkv_b + seg * 3 * NCH + gn;
    const float* wln = (part == 0) ? qn_w + seg * 64 : kn_w + seg * 64;
    const float* bln = (part == 0) ? qn_b + seg * 64 : kn_b + seg * 64;

#pragma unroll
    for (int mi = 0; mi < 2; mi++) {
#pragma unroll
        for (int r = 0; r < 2; r++) {
            int row = m0w + mi * 16 + grp + r * 8;
            bool valid = row < rows;
            int t = rowstart + row;
            size_t ob = ((size_t)(b * NH + hd) * NTOK + t) * HDIM;

            float yv[8][2];
#pragma unroll
            for (int nj = 0; nj < 8; nj++) {
                int d = nj * 8 + tig * 2;
                yv[nj][0] = acc[mi][nj][2 * r]     + bias[d];
                yv[nj][1] = acc[mi][nj][2 * r + 1] + bias[d + 1];
            }

            if (part == 2) {
                if (valid) {
#pragma unroll
                    for (int nj = 0; nj < 8; nj++) {
                        int d = nj * 8 + tig * 2;
                        float v0 = yv[nj][0], v1 = yv[nj][1];
                        float h0 = __half2float(__float2half_rn(v0));
                        float h1 = __half2float(__float2half_rn(v1));
                        *(uint32_t*)(g_vh + ob + d) = packh(v0, v1);
                        *(uint32_t*)(g_vl + ob + d) = packh(v0 - h0, v1 - h1);
                    }
                }
            } else {
                float s = 0.f;
#pragma unroll
                for (int nj = 0; nj < 8; nj++) s += yv[nj][0] + yv[nj][1];
                s += __shfl_xor_sync(0xffffffffu, s, 1);
                s += __shfl_xor_sync(0xffffffffu, s, 2);
                float mu = s * (1.f / 64.f);
                float s2 = 0.f;
#pragma unroll
                for (int nj = 0; nj < 8; nj++) {
                    float d0 = yv[nj][0] - mu, d1 = yv[nj][1] - mu;
                    s2 += d0 * d0 + d1 * d1;
                }
                s2 += __shfl_xor_sync(0xffffffffu, s2, 1);
                s2 += __shfl_xor_sync(0xffffffffu, s2, 2);
                float istd = rsqrtf(s2 * (1.f / 64.f) + 1e-5f);
#pragma unroll
                for (int nj = 0; nj < 8; nj++) {
                    int d = nj * 8 + tig * 2;
                    yv[nj][0] = (yv[nj][0] - mu) * istd * wln[d]     + bln[d];
                    yv[nj][1] = (yv[nj][1] - mu) * istd * wln[d + 1] + bln[d + 1];
                }
                const float* ctp = g_ct + ((size_t)(b * NTOK) + t) * 32;
                const float* stp = g_st + ((size_t)(b * NTOK) + t) * 32;
#pragma unroll
                for (int nj = 0; nj < 4; nj++) {
                    int d = nj * 8 + tig * 2;
                    float cs0 = ctp[d], sn0 = stp[d];
                    float cs1 = ctp[d + 1], sn1 = stp[d + 1];
                    float a0 = yv[nj][0], a1 = yv[nj][1];
                    float b0 = yv[nj + 4][0], b1 = yv[nj + 4][1];
                    yv[nj][0]     = a0 * cs0 - b0 * sn0;
                    yv[nj][1]     = a1 * cs1 - b1 * sn1;
                    yv[nj + 4][0] = b0 * cs0 + a0 * sn0;
                    yv[nj + 4][1] = b1 * cs1 + a1 * sn1;
                }
                if (valid) {
                    if (part == 0) {
#pragma unroll
                        for (int nj = 0; nj < 8; nj++) {
                            int d = nj * 8 + tig * 2;
                            *(uint32_t*)(g_qa + ob + d) = packh(yv[nj][0], yv[nj][1]);
                        }
                    } else {
#pragma unroll
                        for (int nj = 0; nj < 8; nj++) {
                            int d = nj * 8 + tig * 2;
                            float v0 = yv[nj][0], v1 = yv[nj][1];
                            float h0 = __half2float(__float2half_rn(v0));
                            float h1 = __half2float(__float2half_rn(v1));
                            *(uint32_t*)(g_kh + ob + d) = packh(v0, v1);
                            *(uint32_t*)(g_kl + ob + d) = packh(v0 - h0, v1 - h1);
                        }
                    }
                }
            }
        }
    }
}

// ---------------- proj GEMM (per batch) -------------------------------------------
__global__ __launch_bounds__(256, 1) void proj_mma(int b,
                                                   const float* __restrict__ proj_b,
                                                   float* __restrict__ out)
{
    int t17 = blockIdx.y;
    int seg, rowstart, rows;
    tile_map(t17, seg, rowstart, rows);
    int n0 = blockIdx.x * 128;
    size_t arow = (size_t)(b * NTOK + rowstart) * NCH;
    size_t brow = (size_t)(seg * NCH + n0) * NCH;

    float acc[2][8][4];
    gemm_mainloop(g_ao + arow, g_wph + brow, g_wpl + brow, rows, acc);

    const int tid = threadIdx.x, wid = tid >> 5, lane = tid & 31;
    const int m0w = (wid & 3) * 32;
    const int n0w = (wid >> 2) * 64;
    const int grp = lane >> 2, tig = lane & 3;
    const float* bias = proj_b + seg * NCH + n0;
    float* Cout = out + (size_t)(b * NTOK + rowstart) * NCH + n0;

#pragma unroll
    for (int mi = 0; mi < 2; mi++) {
        int r0 = m0w + mi * 16 + grp;
        int r1 = r0 + 8;
#pragma unroll
        for (int nj = 0; nj < 8; nj++) {
            int n = n0w + nj * 8 + tig * 2;
            float b0 = bias[n], b1 = bias[n + 1];
            if (r0 < rows) {
                float2 v = make_float2(acc[mi][nj][0] + b0, acc[mi][nj][1] + b1);
                *(float2*)(Cout + (size_t)r0 * NCH + n) = v;
            }
            if (r1 < rows) {
                float2 v = make_float2(acc[mi][nj][2] + b0, acc[mi][nj][3] + b1);
                *(float2*)(Cout + (size_t)r1 * NCH + n) = v;
            }
        }
    }
}

// ---------------- flash attention: 64-q tiles, 128 thr, per batch ----------------
#define FROWB 144
#define FARR  (64 * FROWB)          // 9216
#define FSMEM (9 * FARR)            // 82944

__device__ __forceinline__ void load_kv_stage(uint32_t dst, size_t hb, int t0)
{
    const int tid = threadIdx.x;
#pragma unroll
    for (int i = 0; i < 4; i++) {
        int idx = tid + i * 128;
        int row = idx >> 3;
        int c16 = idx & 7;
        size_t off = hb + (size_t)(t0 + row) * HDIM + c16 * 8;
        uint32_t d = dst + row * FROWB + c16 * 16;
        cp16(d,            g_kh + off);
        cp16(d + FARR,     g_kl + off);
        cp16(d + 2 * FARR, g_vh + off);
        cp16(d + 3 * FARR, g_vl + off);
    }
}

__global__ __launch_bounds__(128, 2) void flash_mma(int b)
{
    extern __shared__ char fsm[];
    uint32_t sb = smem_u32(fsm);
    const uint32_t Qs = sb;
    const uint32_t KV = sb + FARR;

    const int qt = (gridDim.x - 1) - blockIdx.x;   // big tiles first
    const int h = blockIdx.y;
    const int q0 = qt * 64;
    const int tid = threadIdx.x, wid = tid >> 5, lane = tid & 31;
    const size_t hb = ((size_t)(b * NH + h)) * NTOK * HDIM;

#pragma unroll
    for (int i = 0; i < 4; i++) {
        int idx = tid + i * 128;
        int row = idx >> 3;
        int c16 = idx & 7;
        size_t off = hb + (size_t)(q0 + row) * HDIM + c16 * 8;
        if (idx < 512)
            cp16(Qs + row * FROWB + c16 * 16, g_qa + off);
    }
    CP_COMMIT();
    load_kv_stage(KV, hb, 0);
    CP_COMMIT();
    CP_WAIT(1);
    __syncthreads();

    const int a_row = lane & 15;
    const int a_kh  = (lane >> 4) << 3;
    uint32_t qf[4][4];
#pragma unroll
    for (int kk = 0; kk < 4; kk++) {
        uint32_t addr = Qs + (wid * 16 + a_row) * FROWB + (kk * 16 + a_kh) * 2;
        ldm_x4(qf[kk][0], qf[kk][1], qf[kk][2], qf[kk][3], addr);
    }

    const int grp = lane >> 2, tig = lane & 3;
    const int b_row = (lane & 7) + ((lane >> 4) << 3);
    const int b_kh  = ((lane >> 3) & 1) << 3;
    const int v_row = (lane & 7) + (((lane >> 3) & 1) << 3);
    const int v_col = (lane >> 4) << 3;
    const int row0g = q0 + wid * 16 + grp;

    float m_[2] = {-1e30f, -1e30f}, l_[2] = {0.f, 0.f};
    float o[8][4];
#pragma unroll
    for (int nj = 0; nj < 8; nj++)
#pragma unroll
        for (int r = 0; r < 4; r++) o[nj][r] = 0.f;

    for (int kt = 0; kt <= qt; ++kt) {
        uint32_t st = KV + (kt & 1) * 4 * FARR;
        if (kt < qt) {
            load_kv_stage(KV + ((kt + 1) & 1) * 4 * FARR, hb, (kt + 1) * 64);
            CP_COMMIT();
            CP_WAIT(1);
        } else {
            CP_WAIT(0);
        }
        __syncthreads();

        float s[8][4];
#pragma unroll
        for (int nj = 0; nj < 8; nj++)
#pragma unroll
            for (int r = 0; r < 4; r++) s[nj][r] = 0.f;

#pragma unroll
        for (int kk = 0; kk < 4; ++kk) {
            uint32_t kf[8][2];
#pragma unroll
            for (int p = 0; p < 4; p++) {
                uint32_t addr = st + (p * 16 + b_row) * FROWB + (kk * 16 + b_kh) * 2;
                ldm_x4(kf[2 * p][0], kf[2 * p][1], kf[2 * p + 1][0], kf[2 * p + 1][1], addr);
            }
#pragma unroll
            for (int nj = 0; nj < 8; nj++)
                mma_f16(s[nj][0], s[nj][1], s[nj][2], s[nj][3],
                        qf[kk][0], qf[kk][1], qf[kk][2], qf[kk][3], kf[nj][0], kf[nj][1]);
#pragma unroll
            for (int p = 0; p < 4; p++) {
                uint32_t addr = st + FARR + (p * 16 + b_row) * FROWB + (kk * 16 + b_kh) * 2;
                ldm_x4(kf[2 * p][0], kf[2 * p][1], kf[2 * p + 1][0], kf[2 * p + 1][1], addr);
            }
#pragma unroll
            for (int nj = 0; nj < 8; nj++)
                mma_f16(s[nj][0], s[nj][1], s[nj][2], s[nj][3],
                        qf[kk][0], qf[kk][1], qf[kk][2], qf[kk][3], kf[nj][0], kf[nj][1]);
        }

#pragma unroll
        for (int nj = 0; nj < 8; nj++) {
#pragma unroll
            for (int r = 0; r < 4; r++) s[nj][r] *= 0.125f;
            if (kt == qt) {
                int col = kt * 64 + nj * 8 + tig * 2;
                if (col > row0g)     s[nj][0] = -1e30f;
                if (col + 1 > row0g) s[nj][1] = -1e30f;
                if (col > row0g + 8)     s[nj][2] = -1e30f;
                if (col + 1 > row0g + 8) s[nj][3] = -1e30f;
            }
        }

#pragma unroll
        for (int r = 0; r < 2; r++) {
            float rmax = -1e30f;
#pragma unroll
            for (int nj = 0; nj < 8; nj++)
                rmax = fmaxf(rmax, fmaxf(s[nj][2 * r], s[nj][2 * r + 1]));
            rmax = fmaxf(rmax, __shfl_xor_sync(0xffffffffu, rmax, 1));
            rmax = fmaxf(rmax, __shfl_xor_sync(0xffffffffu, rmax, 2));
            float mnew = fmaxf(m_[r], rmax);
            float alpha = __expf(m_[r] - mnew);
            float psum = 0.f;
#pragma unroll
            for (int nj = 0; nj < 8; nj++) {
                float p0 = __expf(s[nj][2 * r] - mnew);
                float p1 = __expf(s[nj][2 * r + 1] - mnew);
                s[nj][2 * r] = p0; s[nj][2 * r + 1] = p1;
                psum += p0 + p1;
            }
            psum += __shfl_xor_sync(0xffffffffu, psum, 1);
            psum += __shfl_xor_sync(0xffffffffu, psum, 2);
            l_[r] = l_[r] * alpha + psum;
            m_[r] = mnew;
#pragma unroll
            for (int nj = 0; nj < 8; nj++) {
                o[nj][2 * r] *= alpha;
                o[nj][2 * r + 1] *= alpha;
            }
        }

#pragma unroll
        for (int kk = 0; kk < 4; ++kk) {
            uint32_t pa[4] = {packh(s[2 * kk][0],     s[2 * kk][1]),
                              packh(s[2 * kk][2],     s[2 * kk][3]),
                              packh(s[2 * kk + 1][0], s[2 * kk + 1][1]),
                              packh(s[2 * kk + 1][2], s[2 * kk + 1][3])};
            uint32_t vf[8][2];
#pragma unroll
            for (int p = 0; p < 4; p++) {
                uint32_t addr = st + 2 * FARR + (kk * 16 + v_row) * FROWB + (p * 16 + v_col) * 2;
                ldm_x4_t(vf[2 * p][0], vf[2 * p][1], vf[2 * p + 1][0], vf[2 * p + 1][1], addr);
            }
#pragma unroll
            for (int nj = 0; nj < 8; nj++)
                mma_f16(o[nj][0], o[nj][1], o[nj][2], o[nj][3],
                        pa[0], pa[1], pa[2], pa[3], vf[nj][0], vf[nj][1]);
#pragma unroll
            for (int p = 0; p < 4; p++) {
                uint32_t addr = st + 3 * FARR + (kk * 16 + v_row) * FROWB + (p * 16 + v_col) * 2;
                ldm_x4_t(vf[2 * p][0], vf[2 * p][1], vf[2 * p + 1][0], vf[2 * p + 1][1], addr);
            }
#pragma unroll
            for (int nj = 0; nj < 8; nj++)
                mma_f16(o[nj][0], o[nj][1], o[nj][2], o[nj][3],
                        pa[0], pa[1], pa[2], pa[3], vf[nj][0], vf[nj][1]);
        }
        __syncthreads();
    }

    float inv0 = 1.f / l_[0], inv1 = 1.f / l_[1];
    int r0 = row0g, r1 = row0g + 8;
#pragma unroll
    for (int nj = 0; nj < 8; nj++) {
        int col = h * HDIM + nj * 8 + tig * 2;
        *(uint32_t*)(g_ao + ((size_t)(b * NTOK) + r0) * NCH + col)
            = packh(o[nj][0] * inv0, o[nj][1] * inv0);
        *(uint32_t*)(g_ao + ((size_t)(b * NTOK) + r1) * NCH + col)
            = packh(o[nj][2] * inv1, o[nj][3] * inv1);
    }
}

// --------------------------------- host ----------------------------------------
extern "C" void kernel_launch(void* const* d_in, const int* in_sizes, int n_in,
                              void* d_out, int out_size)
{
    const float *x = nullptr, *qkv_w = nullptr, *qkv_b = nullptr;
    const float *proj_w = nullptr, *proj_b = nullptr;
    const float *qn_w = nullptr, *qn_b = nullptr, *kn_w = nullptr, *kn_b = nullptr;
    const int *pos = nullptr, *tpos = nullptr;
    int n192 = 0;
    for (int i = 0; i < n_in; i++) {
        long sz = in_sizes[i];
        if (sz == (long)NB * NTOK * NCH && x == nullptr) x = (const float*)d_in[i];
        else if (sz == (long)NB * (NTOK - NSEG_T0)) pos = (const int*)d_in[i];
        else if (sz == (long)NB * NSEG_T0) tpos = (const int*)d_in[i];
        else if (sz == 3L * 3 * NCH * NCH) qkv_w = (const float*)d_in[i];
        else if (sz == 3L * 3 * NCH) qkv_b = (const float*)d_in[i];
        else if (sz == 3L * NCH * NCH) proj_w = (const float*)d_in[i];
        else if (sz == 3L * NCH) proj_b = (const float*)d_in[i];
        else if (sz == 3L * HDIM) {
            const float* p = (const float*)d_in[i];
            if (n192 == 0) qn_w = p; else if (n192 == 1) qn_b = p;
            else if (n192 == 2) kn_w = p; else kn_b = p;
            n192++;
        }
    }
    float* out = (float*)d_out;

    __half *p_xa, *p_wqh, *p_wql, *p_wph, *p_wpl;
    cudaGetSymbolAddress((void**)&p_xa, g_xa);
    cudaGetSymbolAddress((void**)&p_wqh, g_wqh);
    cudaGetSymbolAddress((void**)&p_wql, g_wql);
    cudaGetSymbolAddress((void**)&p_wph, g_wph);
    cudaGetSymbolAddress((void**)&p_wpl, g_wpl);

    cudaFuncSetAttribute(qkv_mma, cudaFuncAttributeMaxDynamicSharedMemorySize, GSMEM);
    cudaFuncSetAttribute(proj_mma, cudaFuncAttributeMaxDynamicSharedMemorySize, GSMEM);
    cudaFuncSetAttribute(flash_mma, cudaFuncAttributeMaxDynamicSharedMemorySize, FSMEM);

    // streams: s0 = capture/main (batch 0), s1 = batch 1, s2 = weights/LUT
    static cudaStream_t s1 = nullptr, s2 = nullptr;
    static cudaEvent_t e_fork = nullptr, e_wq = nullptr, e_wp = nullptr, e_b1 = nullptr;
    if (!s1) {
        cudaStreamCreateWithFlags(&s1, cudaStreamNonBlocking);
        cudaStreamCreateWithFlags(&s2, cudaStreamNonBlocking);
        cudaEventCreateWithFlags(&e_fork, cudaEventDisableTiming);
        cudaEventCreateWithFlags(&e_wq, cudaEventDisableTiming);
        cudaEventCreateWithFlags(&e_wp, cudaEventDisableTiming);
        cudaEventCreateWithFlags(&e_b1, cudaEventDisableTiming);
    }

    cudaStream_t s0 = 0;
    cudaEventRecord(e_fork, s0);
    cudaStreamWaitEvent(s1, e_fork, 0);
    cudaStreamWaitEvent(s2, e_fork, 0);

    const long XHALF = (long)NTOK * NCH;   // per-batch x elements

    // s2: shared operands — qkv weights + LUT first (needed soonest), then proj weights
    cvt_split<<<512, 256, 0, s2>>>(qkv_w, p_wqh, p_wql, 3L * 3 * NCH * NCH / 4);
    build_rope_lut<<<(NB * NTOK * 32 + 255) / 256, 256, 0, s2>>>(pos, tpos);
    cudaEventRecord(e_wq, s2);
    cvt_split<<<256, 256, 0, s2>>>(proj_w, p_wph, p_wpl, 3L * NCH * NCH / 4);
    cudaEventRecord(e_wp, s2);

    // s0: batch-0 pipeline
    cvt_half<<<256, 256, 0, s0>>>(x, p_xa, XHALF / 4);
    cudaStreamWaitEvent(s0, e_wq, 0);
    qkv_mma<<<dim3(24, 17), 256, GSMEM, s0>>>(0, qkv_b, qn_w, qn_b, kn_w, kn_b);
    flash_mma<<<dim3(NTOK / 64, NH), 128, FSMEM, s0>>>(0);
    cudaStreamWaitEvent(s0, e_wp, 0);
    proj_mma<<<dim3(8, 17), 256, GSMEM, s0>>>(0, proj_b, out);

    // s1: batch-1 pipeline
    cvt_half<<<256, 256, 0, s1>>>(x + XHALF, p_xa + XHALF, XHALF / 4);
    cudaStreamWaitEvent(s1, e_wq, 0);
    qkv_mma<<<dim3(24, 17), 256, GSMEM, s1>>>(1, qkv_b, qn_w, qn_b, kn_w, kn_b);
    flash_mma<<<dim3(NTOK / 64, NH), 128, FSMEM, s1>>>(1);
    cudaStreamWaitEvent(s1, e_wp, 0);
    proj_mma<<<dim3(8, 17), 256, GSMEM, s1>>>(1, proj_b, out);
    cudaEventRecord(e_b1, s1);

    // join
    cudaStreamWaitEvent(s0, e_b1, 0);
}